// round 1
// baseline (speedup 1.0000x reference)
#include <cuda_runtime.h>

// Problem constants
#define H_ 128
#define W_ 128
#define C_ 32
#define BS_ 8
#define NKP_ 11                      // num_kp + 1
#define NPIX_ (BS_ * NKP_ * H_ * W_) // 1,441,792 pixels
// 8 threads per pixel, each handling 4 channels via float4
#define NTHREADS_ (NPIX_ * 8)

__global__ void __launch_bounds__(256) deform_kernel(
    const float* __restrict__ src,   // (H, W, C)
    const float* __restrict__ mot,   // (NPIX, 2)
    float* __restrict__ out)         // (NPIX, C)
{
    int tid = blockIdx.x * blockDim.x + threadIdx.x;
    if (tid >= NTHREADS_) return;
    int pix = tid >> 3;      // pixel index
    int cg  = tid & 7;       // channel group: 4 channels per float4

    // motion coords (broadcast load: 8 lanes share one pixel)
    float2 g = __ldg(((const float2*)mot) + pix);
    float gx = (g.x + 1.0f) * (W_ * 0.5f) - 0.5f;
    float gy = (g.y + 1.0f) * (H_ * 0.5f) - 0.5f;

    float xwf = floorf(gx);
    float ynf = floorf(gy);
    float fx = gx - xwf;     // 'w'
    float fy = gy - ynf;     // 'n'
    float ex = 1.0f - fx;    // 'e'
    float sy = 1.0f - fy;    // 's'

    int x0 = (int)xwf;
    int y0 = (int)ynf;
    int x1 = x0 + 1;
    int y1 = y0 + 1;

    bool mx0 = (x0 >= 0) & (x0 < W_);
    bool mx1 = (x1 >= 0) & (x1 < W_);
    bool my0 = (y0 >= 0) & (y0 < H_);
    bool my1 = (y1 >= 0) & (y1 < H_);

    float w00 = sy * ex * (float)(my0 & mx0);  // nw
    float w01 = sy * fx * (float)(my0 & mx1);  // ne
    float w10 = fy * ex * (float)(my1 & mx0);  // sw
    float w11 = fy * fx * (float)(my1 & mx1);  // se

    // clamped indices (safe even when weight == 0)
    int xc0 = mx0 ? x0 : 0;
    int xc1 = mx1 ? x1 : 0;
    int yc0 = my0 ? y0 : 0;
    int yc1 = my1 ? y1 : 0;

    const float4* s4 = (const float4*)src;   // (H*W, 8) float4 groups
    // float4 index for (y, x, cg): (y*W + x)*8 + cg
    float4 v00 = __ldg(s4 + ((yc0 * W_ + xc0) << 3) + cg);
    float4 v01 = __ldg(s4 + ((yc0 * W_ + xc1) << 3) + cg);
    float4 v10 = __ldg(s4 + ((yc1 * W_ + xc0) << 3) + cg);
    float4 v11 = __ldg(s4 + ((yc1 * W_ + xc1) << 3) + cg);

    float4 acc;
    acc.x = w00 * v00.x + w01 * v01.x + w10 * v10.x + w11 * v11.x;
    acc.y = w00 * v00.y + w01 * v01.y + w10 * v10.y + w11 * v11.y;
    acc.z = w00 * v00.z + w01 * v01.z + w10 * v10.z + w11 * v11.z;
    acc.w = w00 * v00.w + w01 * v01.w + w10 * v10.w + w11 * v11.w;

    ((float4*)out)[(pix << 3) + cg] = acc;
}

extern "C" void kernel_launch(void* const* d_in, const int* in_sizes, int n_in,
                              void* d_out, int out_size)
{
    const float* src = (const float*)d_in[0];   // source (1,H,W,C)
    const float* mot = (const float*)d_in[1];   // motions (BS,NKP,H,W,2)
    float* out = (float*)d_out;

    const int threads = 256;
    const int blocks = (NTHREADS_ + threads - 1) / threads;  // 45056
    deform_kernel<<<blocks, threads>>>(src, mot, out);
}